// round 14
// baseline (speedup 1.0000x reference)
#include <cuda_runtime.h>
#include <cuda_fp16.h>
#include <cstdint>

#define T_DIM 4
#define B_DIM 64
#define C_DIM 256
#define N_DIM 256
#define HEADS 8
#define TAU 0.5f
#define THRESH 1.0f
#define ATTN_THRESH 0.5f
#define BN_EPS 1e-5f
#define OROWS 512
#define TB_TOT (T_DIM * B_DIM)
#define LO_SCALE 0.00048828125f   // 2^-11, exact power of two

#define SW128(b) ((b) ^ (((b) >> 3) & 0x70))

// ---------------- scratch ----------------
__device__ __align__(16) __half g_s[TB_TOT * N_DIM * 512];     // [tb][n][2c|2c+1] spike hi/lo
__device__ __align__(16) __half g_qk[TB_TOT * N_DIM * OROWS];  // q/k spikes (tb,n,o) fp16
__device__ __align__(16) __half g_y[TB_TOT * N_DIM * C_DIM];   // y = attn*k (tb,n,c) fp16
__device__ __align__(16) __half g_w1[OROWS * 512];             // [o][hi,lo interleaved]
__device__ __align__(16) __half g_w2h[C_DIM * C_DIM];          // [o][c] fp16(w2)
__device__ float g_inv[OROWS], g_add[OROWS];
__device__ float g_inv2[C_DIM], g_add2[C_DIM];

// ---------------- PTX helpers ----------------
__device__ __forceinline__ uint32_t smem_u32(const void* p) {
    uint32_t a;
    asm("{ .reg .u64 t; cvta.to.shared.u64 t, %1; cvt.u32.u64 %0, t; }" : "=r"(a) : "l"(p));
    return a;
}
__device__ __forceinline__ void ldmx4(uint32_t* r, uint32_t addr) {
    asm volatile("ldmatrix.sync.aligned.m8n8.x4.shared.b16 {%0,%1,%2,%3}, [%4];"
        : "=r"(r[0]), "=r"(r[1]), "=r"(r[2]), "=r"(r[3]) : "r"(addr));
}
__device__ __forceinline__ void mma16816(float* c, const uint32_t* a, uint32_t b0, uint32_t b1) {
    asm volatile("mma.sync.aligned.m16n8k16.row.col.f32.f16.f16.f32 "
        "{%0,%1,%2,%3}, {%4,%5,%6,%7}, {%8,%9}, {%0,%1,%2,%3};"
        : "+f"(c[0]), "+f"(c[1]), "+f"(c[2]), "+f"(c[3])
        : "r"(a[0]), "r"(a[1]), "r"(a[2]), "r"(a[3]), "r"(b0), "r"(b1));
}
__device__ __forceinline__ void cpa16(uint32_t dst, const void* src) {
    asm volatile("cp.async.cg.shared.global [%0], [%1], 16;" :: "r"(dst), "l"(src));
}
#define CPA_COMMIT() asm volatile("cp.async.commit_group;" ::: "memory")
#define CPA_WAIT(n)  asm volatile("cp.async.wait_group %0;" :: "n"(n) : "memory")

// ---------------- K0: weight prep + BN ----------------
__global__ void k0_prep(const float* __restrict__ wq, const float* __restrict__ wk,
                        const float* __restrict__ wp, const float* __restrict__ pb,
                        const float* __restrict__ qg, const float* __restrict__ qb,
                        const float* __restrict__ qm, const float* __restrict__ qv,
                        const float* __restrict__ kg, const float* __restrict__ kb,
                        const float* __restrict__ km, const float* __restrict__ kv,
                        const float* __restrict__ pg, const float* __restrict__ pbeta,
                        const float* __restrict__ pm, const float* __restrict__ pv) {
    int r = blockIdx.x;   // 0..767
    int c = threadIdx.x;  // 0..255
    if (r < OROWS) {
        float w = (r < C_DIM) ? wq[r * C_DIM + c] : wk[(r - C_DIM) * C_DIM + c];
        __half hi = __float2half_rn(w);
        float lo = (w - __half2float(hi)) * 2048.f;
        g_w1[r * 512 + 2 * c] = hi;
        g_w1[r * 512 + 2 * c + 1] = __float2half_rn(lo);
        if (c == 0) {
            float iv, ad;
            if (r < C_DIM) { iv = qg[r] * rsqrtf(qv[r] + BN_EPS); ad = qb[r] - qm[r] * iv; }
            else { int o = r - C_DIM; iv = kg[o] * rsqrtf(kv[o] + BN_EPS); ad = kb[o] - km[o] * iv; }
            g_inv[r] = iv; g_add[r] = ad;
        }
    } else {
        int o = r - OROWS;
        g_w2h[o * C_DIM + c] = __float2half_rn(wp[o * C_DIM + c]);
        if (c == 0) {
            float iv = pg[o] * rsqrtf(pv[o] + BN_EPS);
            g_inv2[o] = iv;
            g_add2[o] = pb[o] * iv + pbeta[o] - pm[o] * iv;
        }
    }
}

// ---------------- K1: input LIF + transpose -> g_s ----------------
__global__ __launch_bounds__(1024) void k1_lif_input(const float* __restrict__ x) {
    __shared__ float tile[T_DIM][32][33];
    const int n0 = blockIdx.x * 32, c0 = blockIdx.y * 32, b = blockIdx.z;
    const int tid = threadIdx.x;
    const int cl = tid >> 5, nl = tid & 31;
    const int cl2 = tid & 31, nl2 = tid >> 5;
    float mem = 0.f;
#pragma unroll
    for (int t = 0; t < T_DIM; t++) {
        int tb = t * B_DIM + b;
        float v = x[((size_t)tb * C_DIM + c0 + cl) * N_DIM + n0 + nl];
        mem = mem * TAU + v;
        float sp = (mem >= THRESH) ? 1.f : 0.f;
        mem *= (1.f - sp);
        tile[t][cl][nl] = sp;
    }
    __syncthreads();
#pragma unroll
    for (int t = 0; t < T_DIM; t++) {
        int tb = t * B_DIM + b;
        float s2 = tile[t][cl2][nl2];
        size_t base = ((size_t)tb * N_DIM + n0 + nl2) * 512 + 2 * (c0 + cl2);
        *reinterpret_cast<__half2*>(g_s + base) = __floats2half2_rn(s2, s2 * LO_SCALE);
    }
}

// ---------------- G1F: full-shape GEMM + BN + LIF (membranes in smem) ----------------
// grid (4 mtiles, 2 ntiles, 64 b), t-loop inside; 256 thr = 8 warps (4m x 2n), warp 32x64.
// smem: A 2x16K @0 | B 2x16K @32K | membranes 64K @64K ; stage overlays A region.
#define SMEM_G1F 131072
__global__ __launch_bounds__(256) void g1_fused() {
    extern __shared__ char sm[];
    float* stage = reinterpret_cast<float*>(sm);               // 128x33 fp32 (epilogue)
    float* mem_s = reinterpret_cast<float*>(sm + 65536);       // 128 o x 128 n membranes
    const uint32_t sb = smem_u32(sm);

    const int mtile = blockIdx.x, ntile = blockIdx.y, b = blockIdx.z;
    const int tid = threadIdx.x, wid = tid >> 5, lane = tid & 31;
    const int warp_m = wid >> 1, warp_n = wid & 1;

    const int a_row = warp_m * 32 + (lane & 7) + ((lane >> 3) & 1) * 8;
    const int a_kadd = (lane >> 4) * 8;
    const int b_row = warp_n * 64 + (lane & 7) + (lane >> 4) * 8;
    const int b_kadd = ((lane >> 3) & 1) * 8;

    const __half* Ag = g_w1 + (size_t)(mtile * 128) * 512;

    // zero membranes
    {
        float4 z = make_float4(0.f, 0.f, 0.f, 0.f);
        float4* m4 = reinterpret_cast<float4*>(mem_s);
#pragma unroll
        for (int i = 0; i < 16; i++) m4[tid + i * 256] = z;
    }
    __syncthreads();

    for (int t = 0; t < T_DIM; t++) {
        const int tb = t * B_DIM + b;
        const __half* Bg = g_s + ((size_t)tb * N_DIM + ntile * 128) * 512;

        float acc[2][8][4];
#pragma unroll
        for (int i = 0; i < 2; i++)
#pragma unroll
            for (int j = 0; j < 8; j++)
#pragma unroll
                for (int q = 0; q < 4; q++) acc[i][j][q] = 0.f;

        // prefetch chunk 0
#pragma unroll
        for (int i = 0; i < 4; i++) {
            int idx = tid + i * 256, row = idx >> 3, c16 = idx & 7;
            cpa16(sb + SW128(row * 128 + c16 * 16), Ag + row * 512 + c16 * 8);
            cpa16(sb + 32768u + SW128(row * 128 + c16 * 16), Bg + row * 512 + c16 * 8);
        }
        CPA_COMMIT();

        for (int ch = 0; ch < 8; ch++) {
            const uint32_t bufA = sb + (uint32_t)(ch & 1) * 16384u;
            const uint32_t bufB = sb + 32768u + (uint32_t)(ch & 1) * 16384u;
            if (ch < 7) {
                const int kc = (ch + 1) * 64;
                const uint32_t nA = sb + (uint32_t)((ch + 1) & 1) * 16384u;
                const uint32_t nB = sb + 32768u + (uint32_t)((ch + 1) & 1) * 16384u;
#pragma unroll
                for (int i = 0; i < 4; i++) {
                    int idx = tid + i * 256, row = idx >> 3, c16 = idx & 7;
                    cpa16(nA + SW128(row * 128 + c16 * 16), Ag + row * 512 + kc + c16 * 8);
                    cpa16(nB + SW128(row * 128 + c16 * 16), Bg + row * 512 + kc + c16 * 8);
                }
                CPA_COMMIT();
                CPA_WAIT(1);
            } else {
                CPA_WAIT(0);
            }
            __syncthreads();
#pragma unroll
            for (int k16 = 0; k16 < 4; k16++) {
                uint32_t afr[2][4], bfr[4][4];
#pragma unroll
                for (int mb = 0; mb < 2; mb++)
                    ldmx4(afr[mb], bufA + SW128((a_row + mb * 16) * 128 + (k16 * 16 + a_kadd) * 2));
#pragma unroll
                for (int p = 0; p < 4; p++)
                    ldmx4(bfr[p], bufB + SW128((b_row + p * 16) * 128 + (k16 * 16 + b_kadd) * 2));
#pragma unroll
                for (int mb = 0; mb < 2; mb++)
#pragma unroll
                    for (int p = 0; p < 4; p++) {
                        mma16816(acc[mb][2 * p], afr[mb], bfr[p][0], bfr[p][1]);
                        mma16816(acc[mb][2 * p + 1], afr[mb], bfr[p][2], bfr[p][3]);
                    }
            }
            __syncthreads();
        }

        // epilogue: BN + LIF (membranes in smem) -> fp16 spikes to g_qk (tb,n,o)
        for (int nc = 0; nc < 4; nc++) {
            if (warp_n == (nc >> 1)) {
                int nbb = (nc & 1) * 4;
#pragma unroll
                for (int mb = 0; mb < 2; mb++)
#pragma unroll
                    for (int j = 0; j < 4; j++) {
                        int nb = nbb + j;
                        int o_l = warp_m * 32 + mb * 16 + (lane >> 2);
                        int nn = j * 8 + (lane & 3) * 2;
                        int ng = nc * 32 + nn;   // n within 128-tile
                        float iva = g_inv[mtile * 128 + o_l], ada = g_add[mtile * 128 + o_l];
                        float ivb = g_inv[mtile * 128 + o_l + 8], adb = g_add[mtile * 128 + o_l + 8];
#pragma unroll
                        for (int q = 0; q < 4; q++) {
                            int oo = o_l + (q >> 1) * 8;
                            int nn2 = ng + (q & 1);
                            float v = acc[mb][nb][q] * ((q >> 1) ? ivb : iva) + ((q >> 1) ? adb : ada);
                            float m = mem_s[oo * 128 + nn2] * TAU + v;
                            float sp = (m >= THRESH) ? 1.f : 0.f;
                            mem_s[oo * 128 + nn2] = m * (1.f - sp);
                            stage[oo * 33 + nn + (q & 1)] = sp;
                        }
                    }
            }
            __syncthreads();
            {
                int n_l = tid >> 3, seg = tid & 7;    // 32 n x 8 segs of 16 o
                uint4 o4a, o4b;
                __half* ha = reinterpret_cast<__half*>(&o4a);
                __half* hb = reinterpret_cast<__half*>(&o4b);
#pragma unroll
                for (int j = 0; j < 8; j++)
                    ha[j] = __float2half_rn(stage[(seg * 16 + j) * 33 + n_l]);
#pragma unroll
                for (int j = 0; j < 8; j++)
                    hb[j] = __float2half_rn(stage[(seg * 16 + 8 + j) * 33 + n_l]);
                __half* dst = g_qk + ((size_t)tb * N_DIM + ntile * 128 + nc * 32 + n_l) * OROWS
                                   + mtile * 128 + seg * 16;
                *reinterpret_cast<uint4*>(dst) = o4a;
                *reinterpret_cast<uint4*>(dst + 8) = o4b;
            }
            __syncthreads();
        }
    }
}

// ---------------- K23': head sums + decay memory + attn LIF -> y fp16 ----------------
__global__ __launch_bounds__(256) void k23_attn(const float* __restrict__ alpha_p) {
    const int gw = blockIdx.x * 8 + (threadIdx.x >> 5);
    const int lane = threadIdx.x & 31;
    const int b = gw >> 8, n = gw & 255;
    const float a = *alpha_p;

    float M = 0.f, amem = 0.f;   // per-head (head = lane>>2), replicated across 4 lanes
#pragma unroll
    for (int t = 0; t < T_DIM; t++) {
        const int tb = t * B_DIM + b;
        const __half* row = g_qk + ((size_t)tb * N_DIM + n) * OROWS;
        uint4 qv = *reinterpret_cast<const uint4*>(row + 8 * lane);
        uint4 kv = *reinterpret_cast<const uint4*>(row + 256 + 8 * lane);
        const __half2* q2 = reinterpret_cast<const __half2*>(&qv);
        float Q = 0.f;
#pragma unroll
        for (int j = 0; j < 4; j++) {
            float2 f = __half22float2(q2[j]);
            Q += f.x + f.y;
        }
        Q += __shfl_xor_sync(0xffffffffu, Q, 1, 4);
        Q += __shfl_xor_sync(0xffffffffu, Q, 2, 4);

        M = (1.f - a) * M + a * Q;
        float qs = M + Q;
        amem = amem * TAU + qs;
        float sp = (amem >= ATTN_THRESH) ? 1.f : 0.f;
        amem *= (1.f - sp);

        __half2 s2 = __floats2half2_rn(sp, sp);
        uint4 ov;
        __half2* kp = reinterpret_cast<__half2*>(&kv);
        __half2* op = reinterpret_cast<__half2*>(&ov);
#pragma unroll
        for (int j = 0; j < 4; j++) op[j] = __hmul2(kp[j], s2);
        *reinterpret_cast<uint4*>(g_y + ((size_t)tb * N_DIM + n) * C_DIM + 8 * lane) = ov;
    }
}

// ---------------- G2: GEMM out = BN(W2h @ y + bias), 2-stage  M=256 N=256 K=256 ----------------
__global__ __launch_bounds__(256) void g2_gemm(float* __restrict__ out) {
    extern __shared__ char sm[];
    const uint32_t sb = smem_u32(sm);

    const int mtile = blockIdx.x, ntile = blockIdx.y, tb = blockIdx.z;
    const int tid = threadIdx.x, wid = tid >> 5, lane = tid & 31;
    const int warp_m = wid >> 1, warp_n = wid & 1;

    float acc[2][8][4];
#pragma unroll
    for (int i = 0; i < 2; i++)
#pragma unroll
        for (int j = 0; j < 8; j++)
#pragma unroll
            for (int q = 0; q < 4; q++) acc[i][j][q] = 0.f;

    const int a_row = warp_m * 32 + (lane & 7) + ((lane >> 3) & 1) * 8;
    const int a_kadd = (lane >> 4) * 8;
    const int b_row = warp_n * 64 + (lane & 7) + (lane >> 4) * 8;
    const int b_kadd = ((lane >> 3) & 1) * 8;

    const __half* Ag = g_w2h + (size_t)(mtile * 128) * C_DIM;
    const __half* Bg = g_y + ((size_t)tb * N_DIM + ntile * 128) * C_DIM;

#pragma unroll
    for (int i = 0; i < 4; i++) {
        int idx = tid + i * 256, row = idx >> 3, c16 = idx & 7;
        cpa16(sb + SW128(row * 128 + c16 * 16), Ag + row * C_DIM + c16 * 8);
        cpa16(sb + 32768u + SW128(row * 128 + c16 * 16), Bg + row * C_DIM + c16 * 8);
    }
    CPA_COMMIT();

    for (int ch = 0; ch < 4; ch++) {
        const uint32_t bufA = sb + (uint32_t)(ch & 1) * 16384u;
        const uint32_t bufB = sb + 32768u + (uint32_t)(ch & 1) * 16384u;
        if (ch < 3) {
            const int kc = (ch + 1) * 64;
            const uint32_t nA = sb + (uint32_t)((ch + 1) & 1) * 16384u;
            const uint32_t nB = sb + 32768u + (uint32_t)((ch + 1) & 1) * 16384u;
#pragma unroll
            for (int i = 0; i < 4; i++) {
                int idx = tid + i * 256, row = idx >> 3, c16 = idx & 7;
                cpa16(nA + SW128(row * 128 + c16 * 16), Ag + row * C_DIM + kc + c16 * 8);
                cpa16(nB + SW128(row * 128 + c16 * 16), Bg + row * C_DIM + kc + c16 * 8);
            }
            CPA_COMMIT();
            CPA_WAIT(1);
        } else {
            CPA_WAIT(0);
        }
        __syncthreads();
#pragma unroll
        for (int k16 = 0; k16 < 4; k16++) {
            uint32_t afr[2][4], bfr[4][4];
#pragma unroll
            for (int mb = 0; mb < 2; mb++)
                ldmx4(afr[mb], bufA + SW128((a_row + mb * 16) * 128 + (k16 * 16 + a_kadd) * 2));
#pragma unroll
            for (int p = 0; p < 4; p++)
                ldmx4(bfr[p], bufB + SW128((b_row + p * 16) * 128 + (k16 * 16 + b_kadd) * 2));
#pragma unroll
            for (int mb = 0; mb < 2; mb++)
#pragma unroll
                for (int p = 0; p < 4; p++) {
                    mma16816(acc[mb][2 * p], afr[mb], bfr[p][0], bfr[p][1]);
                    mma16816(acc[mb][2 * p + 1], afr[mb], bfr[p][2], bfr[p][3]);
                }
        }
        __syncthreads();
    }

#pragma unroll
    for (int mb = 0; mb < 2; mb++) {
        int o0 = mtile * 128 + warp_m * 32 + mb * 16 + (lane >> 2);
        float iva = g_inv2[o0], ada = g_add2[o0];
        float ivb = g_inv2[o0 + 8], adb = g_add2[o0 + 8];
#pragma unroll
        for (int nb = 0; nb < 8; nb++) {
            int n_g = ntile * 128 + warp_n * 64 + nb * 8 + (lane & 3) * 2;
            float2 v0 = make_float2(acc[mb][nb][0] * iva + ada, acc[mb][nb][1] * iva + ada);
            float2 v1 = make_float2(acc[mb][nb][2] * ivb + adb, acc[mb][nb][3] * ivb + adb);
            *reinterpret_cast<float2*>(out + ((size_t)tb * C_DIM + o0) * N_DIM + n_g) = v0;
            *reinterpret_cast<float2*>(out + ((size_t)tb * C_DIM + o0 + 8) * N_DIM + n_g) = v1;
        }
    }
}

// ---------------- launch ----------------
extern "C" void kernel_launch(void* const* d_in, const int* in_sizes, int n_in,
                              void* d_out, int out_size) {
    const float* x       = (const float*)d_in[0];
    const float* q_w     = (const float*)d_in[1];
    const float* q_gamma = (const float*)d_in[2];
    const float* q_beta  = (const float*)d_in[3];
    const float* q_mean  = (const float*)d_in[4];
    const float* q_var   = (const float*)d_in[5];
    const float* k_w     = (const float*)d_in[6];
    const float* k_gamma = (const float*)d_in[7];
    const float* k_beta  = (const float*)d_in[8];
    const float* k_mean  = (const float*)d_in[9];
    const float* k_var   = (const float*)d_in[10];
    const float* proj_w  = (const float*)d_in[11];
    const float* proj_b  = (const float*)d_in[12];
    const float* proj_g  = (const float*)d_in[13];
    const float* proj_be = (const float*)d_in[14];
    const float* proj_m  = (const float*)d_in[15];
    const float* proj_v  = (const float*)d_in[16];
    const float* alpha   = (const float*)d_in[17];
    float* out = (float*)d_out;

    cudaFuncSetAttribute(g1_fused, cudaFuncAttributeMaxDynamicSharedMemorySize, SMEM_G1F);
    cudaFuncSetAttribute(g2_gemm, cudaFuncAttributeMaxDynamicSharedMemorySize, 65536);

    k0_prep<<<OROWS + C_DIM, 256>>>(q_w, k_w, proj_w, proj_b,
                                    q_gamma, q_beta, q_mean, q_var,
                                    k_gamma, k_beta, k_mean, k_var,
                                    proj_g, proj_be, proj_m, proj_v);
    {
        dim3 grid(N_DIM / 32, C_DIM / 32, B_DIM);
        k1_lif_input<<<grid, 1024>>>(x);
    }
    {
        dim3 grid(4, 2, B_DIM);
        g1_fused<<<grid, 256, SMEM_G1F>>>();
    }
    {
        k23_attn<<<B_DIM * N_DIM / 8, 256>>>(alpha);
    }
    {
        dim3 grid(2, 2, TB_TOT);
        g2_gemm<<<grid, 256, 65536>>>(out);
    }
}

// round 15
// speedup vs baseline: 1.7738x; 1.7738x over previous
#include <cuda_runtime.h>
#include <cuda_fp16.h>
#include <cstdint>

#define T_DIM 4
#define B_DIM 64
#define C_DIM 256
#define N_DIM 256
#define HEADS 8
#define TAU 0.5f
#define THRESH 1.0f
#define ATTN_THRESH 0.5f
#define BN_EPS 1e-5f
#define OROWS 512
#define TB_TOT (T_DIM * B_DIM)
#define LO_SCALE 0.00048828125f   // 2^-11, exact power of two

#define SW128(b) ((b) ^ (((b) >> 3) & 0x70))

// ---------------- scratch ----------------
// g_s interleaved-K: column 2c = spike, 2c+1 = spike*2^-11 (pairs w1's hi/lo digits)
__device__ __align__(16) __half g_s[TB_TOT * N_DIM * 512];     // [tb][n][2c|2c+1]
__device__ __align__(16) float  g_u[TB_TOT * N_DIM * OROWS];   // preacts (tb,n,o) fp32
__device__ __align__(16) __half g_y[TB_TOT * N_DIM * C_DIM];   // y = attn*k (tb,n,c) fp16
__device__ __align__(16) __half g_w1[OROWS * 512];             // [o][hi,lo interleaved]
__device__ __align__(16) __half g_w2h[C_DIM * C_DIM];          // [o][c] fp16(w2)
__device__ float g_inv[OROWS], g_add[OROWS];
__device__ float g_inv2[C_DIM], g_add2[C_DIM];

// ---------------- PTX helpers ----------------
__device__ __forceinline__ uint32_t smem_u32(const void* p) {
    uint32_t a;
    asm("{ .reg .u64 t; cvta.to.shared.u64 t, %1; cvt.u32.u64 %0, t; }" : "=r"(a) : "l"(p));
    return a;
}
__device__ __forceinline__ void ldmx4(uint32_t* r, uint32_t addr) {
    asm volatile("ldmatrix.sync.aligned.m8n8.x4.shared.b16 {%0,%1,%2,%3}, [%4];"
        : "=r"(r[0]), "=r"(r[1]), "=r"(r[2]), "=r"(r[3]) : "r"(addr));
}
__device__ __forceinline__ void mma16816(float* c, const uint32_t* a, uint32_t b0, uint32_t b1) {
    asm volatile("mma.sync.aligned.m16n8k16.row.col.f32.f16.f16.f32 "
        "{%0,%1,%2,%3}, {%4,%5,%6,%7}, {%8,%9}, {%0,%1,%2,%3};"
        : "+f"(c[0]), "+f"(c[1]), "+f"(c[2]), "+f"(c[3])
        : "r"(a[0]), "r"(a[1]), "r"(a[2]), "r"(a[3]), "r"(b0), "r"(b1));
}
__device__ __forceinline__ void cpa16(uint32_t dst, const void* src) {
    asm volatile("cp.async.cg.shared.global [%0], [%1], 16;" :: "r"(dst), "l"(src));
}
#define CPA_COMMIT() asm volatile("cp.async.commit_group;" ::: "memory")
#define CPA_WAIT(n)  asm volatile("cp.async.wait_group %0;" :: "n"(n) : "memory")

// ---------------- K0: weight prep (w1 split interleaved, w2 hi-only) + BN ----------------
__global__ void k0_prep(const float* __restrict__ wq, const float* __restrict__ wk,
                        const float* __restrict__ wp, const float* __restrict__ pb,
                        const float* __restrict__ qg, const float* __restrict__ qb,
                        const float* __restrict__ qm, const float* __restrict__ qv,
                        const float* __restrict__ kg, const float* __restrict__ kb,
                        const float* __restrict__ km, const float* __restrict__ kv,
                        const float* __restrict__ pg, const float* __restrict__ pbeta,
                        const float* __restrict__ pm, const float* __restrict__ pv) {
    int r = blockIdx.x;   // 0..767
    int c = threadIdx.x;  // 0..255
    if (r < OROWS) {
        float w = (r < C_DIM) ? wq[r * C_DIM + c] : wk[(r - C_DIM) * C_DIM + c];
        __half hi = __float2half_rn(w);
        float lo = (w - __half2float(hi)) * 2048.f;
        g_w1[r * 512 + 2 * c] = hi;
        g_w1[r * 512 + 2 * c + 1] = __float2half_rn(lo);
        if (c == 0) {
            float iv, ad;
            if (r < C_DIM) { iv = qg[r] * rsqrtf(qv[r] + BN_EPS); ad = qb[r] - qm[r] * iv; }
            else { int o = r - C_DIM; iv = kg[o] * rsqrtf(kv[o] + BN_EPS); ad = kb[o] - km[o] * iv; }
            g_inv[r] = iv; g_add[r] = ad;
        }
    } else {
        int o = r - OROWS;
        g_w2h[o * C_DIM + c] = __float2half_rn(wp[o * C_DIM + c]);
        if (c == 0) {
            float iv = pg[o] * rsqrtf(pv[o] + BN_EPS);
            g_inv2[o] = iv;
            g_add2[o] = pb[o] * iv + pbeta[o] - pm[o] * iv;
        }
    }
}

// ---------------- K1: input LIF + transpose -> g_s (tb,n,interleaved c) ----------------
__global__ __launch_bounds__(1024) void k1_lif_input(const float* __restrict__ x) {
    __shared__ float tile[T_DIM][32][33];
    const int n0 = blockIdx.x * 32, c0 = blockIdx.y * 32, b = blockIdx.z;
    const int tid = threadIdx.x;
    const int cl = tid >> 5, nl = tid & 31;
    const int cl2 = tid & 31, nl2 = tid >> 5;
    float mem = 0.f;
#pragma unroll
    for (int t = 0; t < T_DIM; t++) {
        int tb = t * B_DIM + b;
        float v = x[((size_t)tb * C_DIM + c0 + cl) * N_DIM + n0 + nl];
        mem = mem * TAU + v;
        float sp = (mem >= THRESH) ? 1.f : 0.f;
        mem *= (1.f - sp);
        tile[t][cl][nl] = sp;
    }
    __syncthreads();
#pragma unroll
    for (int t = 0; t < T_DIM; t++) {
        int tb = t * B_DIM + b;
        float s2 = tile[t][cl2][nl2];
        size_t base = ((size_t)tb * N_DIM + n0 + nl2) * 512 + 2 * (c0 + cl2);
        *reinterpret_cast<__half2*>(g_s + base) = __floats2half2_rn(s2, s2 * LO_SCALE);
    }
}

// ---------------- G1: GEMM u = BN(W1 @ s), single-sync 2-stage  M=512 N=256 K=512 ----------------
__global__ __launch_bounds__(256) void g1_gemm() {
    extern __shared__ char sm[];
    float* stage = reinterpret_cast<float*>(sm);
    const uint32_t sb = smem_u32(sm);

    const int mtile = blockIdx.x, ntile = blockIdx.y, tb = blockIdx.z;
    const int tid = threadIdx.x, wid = tid >> 5, lane = tid & 31;
    const int warp_m = wid >> 1, warp_n = wid & 1;

    float acc[2][8][4];
#pragma unroll
    for (int i = 0; i < 2; i++)
#pragma unroll
        for (int j = 0; j < 8; j++)
#pragma unroll
            for (int q = 0; q < 4; q++) acc[i][j][q] = 0.f;

    const int a_row = warp_m * 32 + (lane & 7) + ((lane >> 3) & 1) * 8;
    const int a_kadd = (lane >> 4) * 8;
    const int b_row = warp_n * 64 + (lane & 7) + (lane >> 4) * 8;
    const int b_kadd = ((lane >> 3) & 1) * 8;

    const __half* Ag = g_w1 + (size_t)(mtile * 128) * 512;
    const __half* Bg = g_s + ((size_t)tb * N_DIM + ntile * 128) * 512;

#pragma unroll
    for (int i = 0; i < 4; i++) {
        int idx = tid + i * 256, row = idx >> 3, c16 = idx & 7;
        cpa16(sb + SW128(row * 128 + c16 * 16), Ag + row * 512 + c16 * 8);
        cpa16(sb + 32768u + SW128(row * 128 + c16 * 16), Bg + row * 512 + c16 * 8);
    }
    CPA_COMMIT();

    for (int ch = 0; ch < 8; ch++) {
        CPA_WAIT(0);
        __syncthreads();          // single barrier: buffer (ch+1)&1 free, chunk ch ready
        if (ch < 7) {
            const int kc = (ch + 1) * 64;
            const uint32_t nA = sb + (uint32_t)((ch + 1) & 1) * 16384u;
            const uint32_t nB = sb + 32768u + (uint32_t)((ch + 1) & 1) * 16384u;
#pragma unroll
            for (int i = 0; i < 4; i++) {
                int idx = tid + i * 256, row = idx >> 3, c16 = idx & 7;
                cpa16(nA + SW128(row * 128 + c16 * 16), Ag + row * 512 + kc + c16 * 8);
                cpa16(nB + SW128(row * 128 + c16 * 16), Bg + row * 512 + kc + c16 * 8);
            }
            CPA_COMMIT();
        }
        const uint32_t bufA = sb + (uint32_t)(ch & 1) * 16384u;
        const uint32_t bufB = sb + 32768u + (uint32_t)(ch & 1) * 16384u;
#pragma unroll
        for (int k16 = 0; k16 < 4; k16++) {
            uint32_t afr[2][4], bfr[4][4];
#pragma unroll
            for (int mb = 0; mb < 2; mb++)
                ldmx4(afr[mb], bufA + SW128((a_row + mb * 16) * 128 + (k16 * 16 + a_kadd) * 2));
#pragma unroll
            for (int p = 0; p < 4; p++)
                ldmx4(bfr[p], bufB + SW128((b_row + p * 16) * 128 + (k16 * 16 + b_kadd) * 2));
#pragma unroll
            for (int mb = 0; mb < 2; mb++)
#pragma unroll
                for (int p = 0; p < 4; p++) {
                    mma16816(acc[mb][2 * p], afr[mb], bfr[p][0], bfr[p][1]);
                    mma16816(acc[mb][2 * p + 1], afr[mb], bfr[p][2], bfr[p][3]);
                }
        }
    }
    __syncthreads();   // all MMAs done before stage overlays buffer region

    // epilogue: BN + transpose via smem -> g_u (tb, n, o)
    for (int nc = 0; nc < 4; nc++) {
        if (warp_n == (nc >> 1)) {
            int nbb = (nc & 1) * 4;
#pragma unroll
            for (int mb = 0; mb < 2; mb++)
#pragma unroll
                for (int j = 0; j < 4; j++) {
                    int nb = nbb + j;
                    int o_l = warp_m * 32 + mb * 16 + (lane >> 2);
                    int nn = j * 8 + (lane & 3) * 2;
                    float iva = g_inv[mtile * 128 + o_l], ada = g_add[mtile * 128 + o_l];
                    float ivb = g_inv[mtile * 128 + o_l + 8], adb = g_add[mtile * 128 + o_l + 8];
                    stage[o_l * 33 + nn] = acc[mb][nb][0] * iva + ada;
                    stage[o_l * 33 + nn + 1] = acc[mb][nb][1] * iva + ada;
                    stage[(o_l + 8) * 33 + nn] = acc[mb][nb][2] * ivb + adb;
                    stage[(o_l + 8) * 33 + nn + 1] = acc[mb][nb][3] * ivb + adb;
                }
        }
        __syncthreads();
        {
            int n_l = tid >> 3, seg = tid & 7;
            float tmp[16];
#pragma unroll
            for (int j = 0; j < 16; j++) tmp[j] = stage[(seg * 16 + j) * 33 + n_l];
            float4* dst = reinterpret_cast<float4*>(
                g_u + ((size_t)tb * N_DIM + ntile * 128 + nc * 32 + n_l) * OROWS + mtile * 128 + seg * 16);
#pragma unroll
            for (int j = 0; j < 4; j++)
                dst[j] = make_float4(tmp[j * 4], tmp[j * 4 + 1], tmp[j * 4 + 2], tmp[j * 4 + 3]);
        }
        __syncthreads();
    }
}

// ---------------- K23 fused: LIF(u) + head sums + decay memory + attn LIF -> y fp16 ----------------
__global__ __launch_bounds__(256) void k23_fused(const float* __restrict__ alpha_p) {
    const int gw = blockIdx.x * 8 + (threadIdx.x >> 5);  // (b,n)
    const int lane = threadIdx.x & 31;
    const int b = gw >> 8, n = gw & 255;
    const float a = *alpha_p;

    float memq[8], memk[8];
#pragma unroll
    for (int j = 0; j < 8; j++) { memq[j] = 0.f; memk[j] = 0.f; }
    float Ma = 0.f, Mb = 0.f, amA = 0.f, amB = 0.f;

#pragma unroll
    for (int t = 0; t < T_DIM; t++) {
        const int tb = t * B_DIM + b;
        const float4* u4 = reinterpret_cast<const float4*>(g_u + ((size_t)tb * N_DIM + n) * OROWS);
        float4 q0 = u4[lane], q1 = u4[32 + lane];
        float4 k0 = u4[64 + lane], k1 = u4[96 + lane];

        float sq[8], sk[8];
        {
            const float* qv = &q0.x;
            const float* qv1 = &q1.x;
            const float* kv = &k0.x;
            const float* kv1 = &k1.x;
#pragma unroll
            for (int j = 0; j < 4; j++) {
                float m = memq[j] * TAU + qv[j];
                sq[j] = (m >= THRESH) ? 1.f : 0.f;
                memq[j] = m * (1.f - sq[j]);
                m = memq[4 + j] * TAU + qv1[j];
                sq[4 + j] = (m >= THRESH) ? 1.f : 0.f;
                memq[4 + j] = m * (1.f - sq[4 + j]);
                m = memk[j] * TAU + kv[j];
                sk[j] = (m >= THRESH) ? 1.f : 0.f;
                memk[j] = m * (1.f - sk[j]);
                m = memk[4 + j] * TAU + kv1[j];
                sk[4 + j] = (m >= THRESH) ? 1.f : 0.f;
                memk[4 + j] = m * (1.f - sk[4 + j]);
            }
        }
        float pA = sq[0] + sq[1] + sq[2] + sq[3];
        float pB = sq[4] + sq[5] + sq[6] + sq[7];
#pragma unroll
        for (int off = 4; off > 0; off >>= 1) {
            pA += __shfl_xor_sync(0xffffffffu, pA, off, 8);
            pB += __shfl_xor_sync(0xffffffffu, pB, off, 8);
        }
        Ma = (1.f - a) * Ma + a * pA;
        float qsA = Ma + pA;
        amA = amA * TAU + qsA;
        float spA = (amA >= ATTN_THRESH) ? 1.f : 0.f;
        amA *= (1.f - spA);

        Mb = (1.f - a) * Mb + a * pB;
        float qsB = Mb + pB;
        amB = amB * TAU + qsB;
        float spB = (amB >= ATTN_THRESH) ? 1.f : 0.f;
        amB *= (1.f - spB);

        __half* yrow = g_y + ((size_t)tb * N_DIM + n) * C_DIM;
        uint2 oA, oB;
        __half2* hA = reinterpret_cast<__half2*>(&oA);
        __half2* hB = reinterpret_cast<__half2*>(&oB);
        hA[0] = __floats2half2_rn(sk[0] * spA, sk[1] * spA);
        hA[1] = __floats2half2_rn(sk[2] * spA, sk[3] * spA);
        hB[0] = __floats2half2_rn(sk[4] * spB, sk[5] * spB);
        hB[1] = __floats2half2_rn(sk[6] * spB, sk[7] * spB);
        *reinterpret_cast<uint2*>(yrow + 4 * lane) = oA;
        *reinterpret_cast<uint2*>(yrow + 128 + 4 * lane) = oB;
    }
}

// ---------------- G2: GEMM out = BN(W2h @ y + bias), single-sync 2-stage  M=256 N=256 K=256 ----------------
__global__ __launch_bounds__(256) void g2_gemm(float* __restrict__ out) {
    extern __shared__ char sm[];
    const uint32_t sb = smem_u32(sm);

    const int mtile = blockIdx.x, ntile = blockIdx.y, tb = blockIdx.z;
    const int tid = threadIdx.x, wid = tid >> 5, lane = tid & 31;
    const int warp_m = wid >> 1, warp_n = wid & 1;

    float acc[2][8][4];
#pragma unroll
    for (int i = 0; i < 2; i++)
#pragma unroll
        for (int j = 0; j < 8; j++)
#pragma unroll
            for (int q = 0; q < 4; q++) acc[i][j][q] = 0.f;

    const int a_row = warp_m * 32 + (lane & 7) + ((lane >> 3) & 1) * 8;
    const int a_kadd = (lane >> 4) * 8;
    const int b_row = warp_n * 64 + (lane & 7) + (lane >> 4) * 8;
    const int b_kadd = ((lane >> 3) & 1) * 8;

    const __half* Ag = g_w2h + (size_t)(mtile * 128) * C_DIM;
    const __half* Bg = g_y + ((size_t)tb * N_DIM + ntile * 128) * C_DIM;

#pragma unroll
    for (int i = 0; i < 4; i++) {
        int idx = tid + i * 256, row = idx >> 3, c16 = idx & 7;
        cpa16(sb + SW128(row * 128 + c16 * 16), Ag + row * C_DIM + c16 * 8);
        cpa16(sb + 32768u + SW128(row * 128 + c16 * 16), Bg + row * C_DIM + c16 * 8);
    }
    CPA_COMMIT();

    for (int ch = 0; ch < 4; ch++) {
        CPA_WAIT(0);
        __syncthreads();
        if (ch < 3) {
            const int kc = (ch + 1) * 64;
            const uint32_t nA = sb + (uint32_t)((ch + 1) & 1) * 16384u;
            const uint32_t nB = sb + 32768u + (uint32_t)((ch + 1) & 1) * 16384u;
#pragma unroll
            for (int i = 0; i < 4; i++) {
                int idx = tid + i * 256, row = idx >> 3, c16 = idx & 7;
                cpa16(nA + SW128(row * 128 + c16 * 16), Ag + row * C_DIM + kc + c16 * 8);
                cpa16(nB + SW128(row * 128 + c16 * 16), Bg + row * C_DIM + kc + c16 * 8);
            }
            CPA_COMMIT();
        }
        const uint32_t bufA = sb + (uint32_t)(ch & 1) * 16384u;
        const uint32_t bufB = sb + 32768u + (uint32_t)(ch & 1) * 16384u;
#pragma unroll
        for (int k16 = 0; k16 < 4; k16++) {
            uint32_t afr[2][4], bfr[4][4];
#pragma unroll
            for (int mb = 0; mb < 2; mb++)
                ldmx4(afr[mb], bufA + SW128((a_row + mb * 16) * 128 + (k16 * 16 + a_kadd) * 2));
#pragma unroll
            for (int p = 0; p < 4; p++)
                ldmx4(bfr[p], bufB + SW128((b_row + p * 16) * 128 + (k16 * 16 + b_kadd) * 2));
#pragma unroll
            for (int mb = 0; mb < 2; mb++)
#pragma unroll
                for (int p = 0; p < 4; p++) {
                    mma16816(acc[mb][2 * p], afr[mb], bfr[p][0], bfr[p][1]);
                    mma16816(acc[mb][2 * p + 1], afr[mb], bfr[p][2], bfr[p][3]);
                }
        }
    }

    // epilogue: BN + bias, direct store to out (tb, o, n)
#pragma unroll
    for (int mb = 0; mb < 2; mb++) {
        int o0 = mtile * 128 + warp_m * 32 + mb * 16 + (lane >> 2);
        float iva = g_inv2[o0], ada = g_add2[o0];
        float ivb = g_inv2[o0 + 8], adb = g_add2[o0 + 8];
#pragma unroll
        for (int nb = 0; nb < 8; nb++) {
            int n_g = ntile * 128 + warp_n * 64 + nb * 8 + (lane & 3) * 2;
            float2 v0 = make_float2(acc[mb][nb][0] * iva + ada, acc[mb][nb][1] * iva + ada);
            float2 v1 = make_float2(acc[mb][nb][2] * ivb + adb, acc[mb][nb][3] * ivb + adb);
            *reinterpret_cast<float2*>(out + ((size_t)tb * C_DIM + o0) * N_DIM + n_g) = v0;
            *reinterpret_cast<float2*>(out + ((size_t)tb * C_DIM + o0 + 8) * N_DIM + n_g) = v1;
        }
    }
}

// ---------------- launch ----------------
extern "C" void kernel_launch(void* const* d_in, const int* in_sizes, int n_in,
                              void* d_out, int out_size) {
    const float* x       = (const float*)d_in[0];
    const float* q_w     = (const float*)d_in[1];
    const float* q_gamma = (const float*)d_in[2];
    const float* q_beta  = (const float*)d_in[3];
    const float* q_mean  = (const float*)d_in[4];
    const float* q_var   = (const float*)d_in[5];
    const float* k_w     = (const float*)d_in[6];
    const float* k_gamma = (const float*)d_in[7];
    const float* k_beta  = (const float*)d_in[8];
    const float* k_mean  = (const float*)d_in[9];
    const float* k_var   = (const float*)d_in[10];
    const float* proj_w  = (const float*)d_in[11];
    const float* proj_b  = (const float*)d_in[12];
    const float* proj_g  = (const float*)d_in[13];
    const float* proj_be = (const float*)d_in[14];
    const float* proj_m  = (const float*)d_in[15];
    const float* proj_v  = (const float*)d_in[16];
    const float* alpha   = (const float*)d_in[17];
    float* out = (float*)d_out;

    cudaFuncSetAttribute(g1_gemm, cudaFuncAttributeMaxDynamicSharedMemorySize, 65536);
    cudaFuncSetAttribute(g2_gemm, cudaFuncAttributeMaxDynamicSharedMemorySize, 65536);

    k0_prep<<<OROWS + C_DIM, 256>>>(q_w, k_w, proj_w, proj_b,
                                    q_gamma, q_beta, q_mean, q_var,
                                    k_gamma, k_beta, k_mean, k_var,
                                    proj_g, proj_be, proj_m, proj_v);
    {
        dim3 grid(N_DIM / 32, C_DIM / 32, B_DIM);
        k1_lif_input<<<grid, 1024>>>(x);
    }
    {
        dim3 grid(4, 2, TB_TOT);
        g1_gemm<<<grid, 256, 65536>>>();
    }
    {
        k23_fused<<<B_DIM * N_DIM / 8, 256>>>(alpha);
    }
    {
        dim3 grid(2, 2, TB_TOT);
        g2_gemm<<<grid, 256, 65536>>>(out);
    }
}